// round 14
// baseline (speedup 1.0000x reference)
#include <cuda_runtime.h>
#include <cuda_fp16.h>
#include <cstdint>

// ---------------------------------------------------------------------------
// Problem constants
// ---------------------------------------------------------------------------
#define B_DIM 4096
#define H_DIM 1024
#define N_GATES 4096       // 4*H
#define K_DIM  2048        // D + H

// GEMM tiling (single-pass fp16 HMMA, 64x32 warp tiles, 3 CTAs/SM)
#define BM 128
#define BN 128
#define BK 32              // 32 fp16 = 64 B rows
#define STAGES 4
#define NT (K_DIM / BK)    // 64 k-tiles
#define NTHREADS 256

// smem per stage: A 128x64B + B 128x64B = 16384 B
#define A_TILE_BYTES 8192
#define B_TILE_BYTES 8192
#define STAGE_BYTES (A_TILE_BYTES + B_TILE_BYTES)           // 16384
#define OFF_B A_TILE_BYTES
#define SMEM_TOTAL (STAGES * STAGE_BYTES)                   // 65536 -> 3 CTAs/SM

// ---------------------------------------------------------------------------
// Scratch (device globals). gB/gBias GATE-INTERLEAVED: n' = j*4+g.
// ---------------------------------------------------------------------------
__device__ __half gA[(size_t)B_DIM * K_DIM];
__device__ __half gB[(size_t)N_GATES * K_DIM];
__device__ float gBias[N_GATES];

// ---------------------------------------------------------------------------
// PTX helpers (sm_80+ portable)
// ---------------------------------------------------------------------------
__device__ __forceinline__ uint32_t smem_u32(const void* p) {
    uint32_t a;
    asm("{ .reg .u64 t; cvta.to.shared.u64 t, %1; cvt.u32.u64 %0, t; }" : "=r"(a) : "l"(p));
    return a;
}

#define CP_ASYNC16(dst, src) \
    asm volatile("cp.async.cg.shared.global [%0], [%1], 16;" \
                 :: "r"(dst), "l"(src) : "memory")
#define CP_COMMIT() asm volatile("cp.async.commit_group;" ::: "memory")
#define CP_WAIT(n)  asm volatile("cp.async.wait_group %0;" :: "n"(n) : "memory")

#define LDSM_X4(r, addr) \
    asm volatile("ldmatrix.sync.aligned.m8n8.x4.shared.b16 {%0,%1,%2,%3}, [%4];" \
                 : "=r"((r)[0]), "=r"((r)[1]), "=r"((r)[2]), "=r"((r)[3]) : "r"(addr))

__device__ __forceinline__ void mma_f16(float* d, const uint32_t* a, const uint32_t* b) {
    asm volatile(
        "mma.sync.aligned.m16n8k16.row.col.f32.f16.f16.f32 "
        "{%0,%1,%2,%3}, {%4,%5,%6,%7}, {%8,%9}, {%0,%1,%2,%3};"
        : "+f"(d[0]), "+f"(d[1]), "+f"(d[2]), "+f"(d[3])
        : "r"(a[0]), "r"(a[1]), "r"(a[2]), "r"(a[3]), "r"(b[0]), "r"(b[1]));
}

__device__ __forceinline__ float sigmoidf_(float v) {
    return 1.0f / (1.0f + __expf(-v));
}

// ---------------------------------------------------------------------------
// Conversion kernel:
//   blocks [0, 8192):      A = [x | h0]  -> gA   (row-identity)
//   blocks [8192, 16384):  B = [wih|whh] -> gB   (rows permuted j*4+g)
//   blocks [16384, 16400): permuted bias sum
// ---------------------------------------------------------------------------
__global__ __launch_bounds__(256)
void convert_all(const float* __restrict__ x,   const float* __restrict__ h0,
                 const float* __restrict__ wih, const float* __restrict__ whh,
                 const float* __restrict__ b_ih, const float* __restrict__ b_hh)
{
    const int bid = blockIdx.x;
    const int tid = threadIdx.x;

    if (bid >= 16384) {                       // bias
        const int np = (bid - 16384) * 256 + tid;        // 0..4095
        const int r = ((np & 3) << 10) | (np >> 2);      // orig row g*1024+j
        gBias[np] = b_ih[r] + b_hh[r];
        return;
    }

    const bool isA = (bid < 8192);
    const int idx = (isA ? bid : bid - 8192) * 256 + tid;  // 4-elem group id
    const int row = idx >> 9;                              // output row
    const int col = (idx & 511) << 2;                      // K column

    int srow = row;
    const float *s0, *s1;
    if (isA) { s0 = x; s1 = h0; }
    else     { s0 = wih; s1 = whh; srow = ((row & 3) << 10) | (row >> 2); }

    const float* src = (col < 1024) ? (s0 + (size_t)srow * 1024 + col)
                                    : (s1 + (size_t)srow * 1024 + (col - 1024));
    float4 v = *reinterpret_cast<const float4*>(src);
    __half2 h01 = __floats2half2_rn(v.x, v.y);
    __half2 h23 = __floats2half2_rn(v.z, v.w);
    __half* dst = isA ? gA : gB;
    const size_t o = (size_t)row * K_DIM + col;
    *reinterpret_cast<__half2*>(dst + o)     = h01;
    *reinterpret_cast<__half2*>(dst + o + 2) = h23;
}

// ---------------------------------------------------------------------------
// Fused single-pass fp16 GEMM + LSTM epilogue, 3 CTAs/SM (24 warps).
//   gates = A @ B^T (gate-interleaved cols), fp32 accumulate.
//   Inner loop register-lean: per ks load 2 B frags, then per mt one A frag
//   feeding its 8 MMAs. 6 warps/SMSP hide the LDSM->MMA heads.
// SMEM: 64B rows, chunk' = chunk ^ ((row>>1)&3) (conflict-free both ways).
// ---------------------------------------------------------------------------
__global__ __launch_bounds__(NTHREADS, 3)
void lstm_gemm_fused(const float* __restrict__ c0, float* __restrict__ out)
{
    extern __shared__ char smem[];
    const uint32_t sb = smem_u32(smem);
    const int tid  = threadIdx.x;
    const int wid  = tid >> 5;
    const int lane = tid & 31;
    const int warp_m = wid >> 2;    // 0..1, 64 rows each
    const int warp_n = wid & 3;     // 0..3, 32 cols each

    const int bm = blockIdx.y * BM;
    const int bn = blockIdx.x * BN;

    float acc[4][4][4];             // [mt][nt][frag]
    #pragma unroll
    for (int mt = 0; mt < 4; mt++)
        #pragma unroll
        for (int nt = 0; nt < 4; nt++)
            #pragma unroll
            for (int j = 0; j < 4; j++)
                acc[mt][nt][j] = 0.0f;

    // ---- ldmatrix addressing ----
    const int a_row = warp_m * 64 + (lane & 15);              // + mt*16
    const int s_a   = (a_row >> 1) & 3;
    const int a_c0  = lane >> 4;                              // 0/1
    const int b_row = warp_n * 32 + ((lane >> 4) << 3) + (lane & 7);  // + g*16
    const int s_b   = (b_row >> 1) & 3;
    const int b_c0  = (lane >> 3) & 1;

    // ---- cp.async addressing: A 512 chunks + B 512 chunks, 4 per thread ----
    const int r0 = tid >> 2;                 // 0..63
    const int cc = tid & 3;                  // 16B chunk
    const uint32_t dstoff = (uint32_t)(r0 * 64 + ((cc ^ ((r0 >> 1) & 3)) << 4));
    const __half* pA = gA + (size_t)(bm + r0) * K_DIM + cc * 8;
    const __half* pB = gB + (size_t)(bn + r0) * K_DIM + cc * 8;
    const size_t HSTEP = (size_t)64 * K_DIM;   // +64 rows

    #define LOAD_STAGE(bufidx, k0) do {                                         \
        const uint32_t s_ = sb + (bufidx) * STAGE_BYTES + dstoff;               \
        CP_ASYNC16(s_,                  pA + (k0));                             \
        CP_ASYNC16(s_ + 4096,           pA + (k0) + HSTEP);                     \
        CP_ASYNC16(s_ + OFF_B,          pB + (k0));                             \
        CP_ASYNC16(s_ + OFF_B + 4096,   pB + (k0) + HSTEP);                     \
    } while (0)

    // prologue: stages 0..2
    #pragma unroll
    for (int s = 0; s < STAGES - 1; s++) {
        LOAD_STAGE(s, s * BK);
        CP_COMMIT();
    }

    int cbuf = 0, lbuf = STAGES - 1;
    for (int t = 0; t < NT; t++) {
        CP_WAIT(STAGES - 2);
        __syncthreads();
        if (t + STAGES - 1 < NT)
            LOAD_STAGE(lbuf, (t + STAGES - 1) * BK);
        CP_COMMIT();

        const uint32_t stage = sb + cbuf * STAGE_BYTES;
        #pragma unroll
        for (int ks = 0; ks < 2; ks++) {
            // B fragments first (8 regs live)
            uint32_t b_fr[2][4];
            const int cb = ((ks * 2 + b_c0) ^ s_b) << 4;
            #pragma unroll
            for (int g = 0; g < 2; g++) {
                const uint32_t ba = stage + OFF_B + (b_row + g * 16) * 64 + cb;
                LDSM_X4(b_fr[g], ba);
            }
            // Per-mt A fragment feeding its 8 MMAs (4 regs live)
            const int ca = ((ks * 2 + a_c0) ^ s_a) << 4;
            #pragma unroll
            for (int mt = 0; mt < 4; mt++) {
                uint32_t a_fr[4];
                const uint32_t aa = stage + (a_row + mt * 16) * 64 + ca;
                LDSM_X4(a_fr, aa);
                #pragma unroll
                for (int g = 0; g < 2; g++)
                    #pragma unroll
                    for (int h = 0; h < 2; h++)
                        mma_f16(acc[mt][g * 2 + h], a_fr, &b_fr[g][h * 2]);
            }
        }
        if (++cbuf == STAGES) cbuf = 0;
        if (++lbuf == STAGES) lbuf = 0;
    }

    // ---- fused LSTM epilogue ----
    const int q = lane & 3;
    const bool is_if = ((q & 1) == 0);

    float bsum[4][2];
    #pragma unroll
    for (int nt = 0; nt < 4; nt++) {
        const int c = bn + warp_n * 32 + nt * 8 + q * 2;
        bsum[nt][0] = gBias[c];
        bsum[nt][1] = gBias[c + 1];
    }

    #pragma unroll
    for (int mt = 0; mt < 4; mt++) {
        const int r = bm + warp_m * 64 + mt * 16 + (lane >> 2);
        #pragma unroll
        for (int nt = 0; nt < 4; nt++) {
            float v0 = acc[mt][nt][0] + bsum[nt][0];
            float v1 = acc[mt][nt][1] + bsum[nt][1];
            float v2 = acc[mt][nt][2] + bsum[nt][0];
            float v3 = acc[mt][nt][3] + bsum[nt][1];
            const float o0 = __shfl_xor_sync(0xffffffffu, v0, 1);
            const float o1 = __shfl_xor_sync(0xffffffffu, v1, 1);
            const float o2 = __shfl_xor_sync(0xffffffffu, v2, 1);
            const float o3 = __shfl_xor_sync(0xffffffffu, v3, 1);

            const float gi0 = is_if ? v0 : o0;
            const float gf0 = is_if ? v1 : o1;
            const float gg0 = is_if ? o0 : v0;
            const float go0 = is_if ? o1 : v1;
            const float gi1 = is_if ? v2 : o2;
            const float gf1 = is_if ? v3 : o3;
            const float gg1 = is_if ? o2 : v2;
            const float go1 = is_if ? o3 : v3;

            const int j = (bn >> 2) + warp_n * 8 + nt * 2 + (q >> 1);
            const float c0v0 = c0[(size_t)r * H_DIM + j];
            const float c0v1 = c0[(size_t)(r + 8) * H_DIM + j];

            const float cn0 = sigmoidf_(gf0) * c0v0 + sigmoidf_(gi0) * tanhf(gg0);
            const float cn1 = sigmoidf_(gf1) * c0v1 + sigmoidf_(gi1) * tanhf(gg1);
            const float hn0 = sigmoidf_(go0) * tanhf(cn0);
            const float hn1 = sigmoidf_(go1) * tanhf(cn1);

            if (is_if) {
                out[(size_t)r * H_DIM + j]       = hn0;
                out[(size_t)(r + 8) * H_DIM + j] = hn1;
            } else {
                out[(size_t)B_DIM * H_DIM + (size_t)r * H_DIM + j]       = cn0;
                out[(size_t)B_DIM * H_DIM + (size_t)(r + 8) * H_DIM + j] = cn1;
            }
        }
    }
    #undef LOAD_STAGE
}

// ---------------------------------------------------------------------------
// Launch
// ---------------------------------------------------------------------------
extern "C" void kernel_launch(void* const* d_in, const int* in_sizes, int n_in,
                              void* d_out, int out_size)
{
    const float* x    = (const float*)d_in[0];
    const float* h0   = (const float*)d_in[1];
    const float* c0   = (const float*)d_in[2];
    const float* wih  = (const float*)d_in[3];
    const float* whh  = (const float*)d_in[4];
    const float* b_ih = (const float*)d_in[5];
    const float* b_hh = (const float*)d_in[6];
    float* out = (float*)d_out;

    cudaFuncSetAttribute(lstm_gemm_fused,
                         cudaFuncAttributeMaxDynamicSharedMemorySize, SMEM_TOTAL);

    convert_all<<<16400, 256>>>(x, h0, wih, whh, b_ih, b_hh);

    dim3 grid(N_GATES / BN, B_DIM / BM);                 // (32, 32) = 1024 CTAs
    lstm_gemm_fused<<<grid, NTHREADS, SMEM_TOTAL>>>(c0, out);
}

// round 15
// speedup vs baseline: 1.5801x; 1.5801x over previous
#include <cuda_runtime.h>
#include <cuda_fp16.h>
#include <cstdint>

// ---------------------------------------------------------------------------
// Problem constants
// ---------------------------------------------------------------------------
#define B_DIM 4096
#define H_DIM 1024
#define N_GATES 4096       // 4*H
#define K_DIM  2048        // D + H

// GEMM tiling (single-pass fp16 HMMA, 64x32 warp tiles, BK=64, 2 CTAs/SM)
#define BM 128
#define BN 128
#define BK 64              // 64 fp16 = 128 B rows
#define STAGES 3
#define NT (K_DIM / BK)    // 32 k-tiles
#define NTHREADS 256

// smem per stage: A 128x128B + B 128x128B = 32768 B
#define A_TILE_BYTES 16384
#define B_TILE_BYTES 16384
#define STAGE_BYTES (A_TILE_BYTES + B_TILE_BYTES)           // 32768
#define OFF_B A_TILE_BYTES
#define SMEM_TOTAL (STAGES * STAGE_BYTES)                   // 98304 -> 2 CTAs/SM

// ---------------------------------------------------------------------------
// Scratch (device globals). gB/gBias GATE-INTERLEAVED: n' = j*4+g.
// ---------------------------------------------------------------------------
__device__ __half gA[(size_t)B_DIM * K_DIM];
__device__ __half gB[(size_t)N_GATES * K_DIM];
__device__ float gBias[N_GATES];

// ---------------------------------------------------------------------------
// PTX helpers (sm_80+ portable)
// ---------------------------------------------------------------------------
__device__ __forceinline__ uint32_t smem_u32(const void* p) {
    uint32_t a;
    asm("{ .reg .u64 t; cvta.to.shared.u64 t, %1; cvt.u32.u64 %0, t; }" : "=r"(a) : "l"(p));
    return a;
}

#define CP_ASYNC16(dst, src) \
    asm volatile("cp.async.cg.shared.global [%0], [%1], 16;" \
                 :: "r"(dst), "l"(src) : "memory")
#define CP_COMMIT() asm volatile("cp.async.commit_group;" ::: "memory")
#define CP_WAIT(n)  asm volatile("cp.async.wait_group %0;" :: "n"(n) : "memory")

#define LDSM_X4(r, addr) \
    asm volatile("ldmatrix.sync.aligned.m8n8.x4.shared.b16 {%0,%1,%2,%3}, [%4];" \
                 : "=r"((r)[0]), "=r"((r)[1]), "=r"((r)[2]), "=r"((r)[3]) : "r"(addr))

__device__ __forceinline__ void mma_f16(float* d, const uint32_t* a, const uint32_t* b) {
    asm volatile(
        "mma.sync.aligned.m16n8k16.row.col.f32.f16.f16.f32 "
        "{%0,%1,%2,%3}, {%4,%5,%6,%7}, {%8,%9}, {%0,%1,%2,%3};"
        : "+f"(d[0]), "+f"(d[1]), "+f"(d[2]), "+f"(d[3])
        : "r"(a[0]), "r"(a[1]), "r"(a[2]), "r"(a[3]), "r"(b[0]), "r"(b[1]));
}

__device__ __forceinline__ float sigmoidf_(float v) {
    return 1.0f / (1.0f + __expf(-v));
}

// ---------------------------------------------------------------------------
// Conversion kernel:
//   blocks [0, 8192):      A = [x | h0]  -> gA   (row-identity)
//   blocks [8192, 16384):  B = [wih|whh] -> gB   (rows permuted j*4+g)
//   blocks [16384, 16400): permuted bias sum
// ---------------------------------------------------------------------------
__global__ __launch_bounds__(256)
void convert_all(const float* __restrict__ x,   const float* __restrict__ h0,
                 const float* __restrict__ wih, const float* __restrict__ whh,
                 const float* __restrict__ b_ih, const float* __restrict__ b_hh)
{
    const int bid = blockIdx.x;
    const int tid = threadIdx.x;

    if (bid >= 16384) {                       // bias
        const int np = (bid - 16384) * 256 + tid;        // 0..4095
        const int r = ((np & 3) << 10) | (np >> 2);      // orig row g*1024+j
        gBias[np] = b_ih[r] + b_hh[r];
        return;
    }

    const bool isA = (bid < 8192);
    const int idx = (isA ? bid : bid - 8192) * 256 + tid;  // 4-elem group id
    const int row = idx >> 9;                              // output row
    const int col = (idx & 511) << 2;                      // K column

    int srow = row;
    const float *s0, *s1;
    if (isA) { s0 = x; s1 = h0; }
    else     { s0 = wih; s1 = whh; srow = ((row & 3) << 10) | (row >> 2); }

    const float* src = (col < 1024) ? (s0 + (size_t)srow * 1024 + col)
                                    : (s1 + (size_t)srow * 1024 + (col - 1024));
    float4 v = *reinterpret_cast<const float4*>(src);
    __half2 h01 = __floats2half2_rn(v.x, v.y);
    __half2 h23 = __floats2half2_rn(v.z, v.w);
    __half* dst = isA ? gA : gB;
    const size_t o = (size_t)row * K_DIM + col;
    *reinterpret_cast<__half2*>(dst + o)     = h01;
    *reinterpret_cast<__half2*>(dst + o + 2) = h23;
}

// ---------------------------------------------------------------------------
// Fused single-pass fp16 GEMM + LSTM epilogue.
//   gates = A @ B^T (gate-interleaved cols), fp32 accumulate. BK=64, 32 iters.
//   De-phased warps: warp w walks the 4 k16-steps in order (ks0+wid)&3, so
//   LDSM phases and MMA phases of co-resident warps overlap instead of
//   lockstepping after each __syncthreads. Per ks: 6 LDSMs batched, then
//   16 MMAs (single dependency head).
// SMEM: 128B rows, chunk' = chunk ^ (row&7) (conflict-free both directions).
// ---------------------------------------------------------------------------
__global__ __launch_bounds__(NTHREADS, 2)
void lstm_gemm_fused(const float* __restrict__ c0, float* __restrict__ out)
{
    extern __shared__ char smem[];
    const uint32_t sb = smem_u32(smem);
    const int tid  = threadIdx.x;
    const int wid  = tid >> 5;
    const int lane = tid & 31;
    const int warp_m = wid >> 2;    // 0..1, 64 rows each
    const int warp_n = wid & 3;     // 0..3, 32 cols each

    const int bm = blockIdx.y * BM;
    const int bn = blockIdx.x * BN;

    float acc[4][4][4];             // [mt][nt][frag]
    #pragma unroll
    for (int mt = 0; mt < 4; mt++)
        #pragma unroll
        for (int nt = 0; nt < 4; nt++)
            #pragma unroll
            for (int j = 0; j < 4; j++)
                acc[mt][nt][j] = 0.0f;

    // ---- ldmatrix addressing (128B rows, swizzle chunk ^ (row&7)) ----
    const int a_row = warp_m * 64 + (lane & 15);              // + mt*16
    const int s_a   = a_row & 7;
    const int a_c0  = lane >> 4;                              // 0/1
    const int b_row = warp_n * 32 + ((lane >> 4) << 3) + (lane & 7);  // + g*16
    const int s_b   = b_row & 7;
    const int b_c0  = (lane >> 3) & 1;

    // ---- cp.async: A 1024 chunks + B 1024 chunks, 8 per thread ----
    const int r0 = tid >> 3;                 // 0..31
    const int cc = tid & 7;                  // 16B chunk in 128B row
    const uint32_t dstoff = (uint32_t)(r0 * 128 + ((cc ^ (r0 & 7)) << 4));
    const __half* pA = gA + (size_t)(bm + r0) * K_DIM + cc * 8;
    const __half* pB = gB + (size_t)(bn + r0) * K_DIM + cc * 8;
    const size_t RSTEP = (size_t)32 * K_DIM;   // +32 rows ((r0+32j)&7 == r0&7)

    #define LOAD_STAGE(bufidx, k0) do {                                         \
        const uint32_t s_ = sb + (bufidx) * STAGE_BYTES + dstoff;               \
        CP_ASYNC16(s_,                  pA + (k0));                             \
        CP_ASYNC16(s_ + 4096,           pA + (k0) + RSTEP);                     \
        CP_ASYNC16(s_ + 8192,           pA + (k0) + 2 * RSTEP);                 \
        CP_ASYNC16(s_ + 12288,          pA + (k0) + 3 * RSTEP);                 \
        CP_ASYNC16(s_ + OFF_B,          pB + (k0));                             \
        CP_ASYNC16(s_ + OFF_B + 4096,   pB + (k0) + RSTEP);                     \
        CP_ASYNC16(s_ + OFF_B + 8192,   pB + (k0) + 2 * RSTEP);                 \
        CP_ASYNC16(s_ + OFF_B + 12288,  pB + (k0) + 3 * RSTEP);                 \
    } while (0)

    // prologue: stages 0,1
    LOAD_STAGE(0, 0);
    CP_COMMIT();
    LOAD_STAGE(1, BK);
    CP_COMMIT();

    const int ksrot = wid & 3;      // per-warp ks rotation (de-phasing)

    int cbuf = 0, lbuf = 2;
    for (int t = 0; t < NT; t++) {
        CP_WAIT(1);
        __syncthreads();
        if (t + 2 < NT)
            LOAD_STAGE(lbuf, (t + 2) * BK);
        CP_COMMIT();

        const uint32_t stage = sb + cbuf * STAGE_BYTES;
        #pragma unroll
        for (int ks0 = 0; ks0 < 4; ks0++) {
            const int ks = (ks0 + ksrot) & 3;      // rotated walk
            // batch all 6 LDSMs (4 A + 2 B), then 16 MMAs
            uint32_t a_fr[4][4], b_fr[2][4];
            const int ca = ((ks * 2 + a_c0) ^ s_a) << 4;
            #pragma unroll
            for (int mt = 0; mt < 4; mt++) {
                const uint32_t aa = stage + (a_row + mt * 16) * 128 + ca;
                LDSM_X4(a_fr[mt], aa);
            }
            const int cb = ((ks * 2 + b_c0) ^ s_b) << 4;
            #pragma unroll
            for (int g = 0; g < 2; g++) {
                const uint32_t ba = stage + OFF_B + (b_row + g * 16) * 128 + cb;
                LDSM_X4(b_fr[g], ba);
            }
            #pragma unroll
            for (int g = 0; g < 2; g++)
                #pragma unroll
                for (int h = 0; h < 2; h++)
                    #pragma unroll
                    for (int mt = 0; mt < 4; mt++)
                        mma_f16(acc[mt][g * 2 + h], a_fr[mt], &b_fr[g][h * 2]);
        }
        if (++cbuf == STAGES) cbuf = 0;
        if (++lbuf == STAGES) lbuf = 0;
    }

    // ---- fused LSTM epilogue ----
    const int q = lane & 3;
    const bool is_if = ((q & 1) == 0);

    float bsum[4][2];
    #pragma unroll
    for (int nt = 0; nt < 4; nt++) {
        const int c = bn + warp_n * 32 + nt * 8 + q * 2;
        bsum[nt][0] = gBias[c];
        bsum[nt][1] = gBias[c + 1];
    }

    #pragma unroll
    for (int mt = 0; mt < 4; mt++) {
        const int r = bm + warp_m * 64 + mt * 16 + (lane >> 2);
        #pragma unroll
        for (int nt = 0; nt < 4; nt++) {
            float v0 = acc[mt][nt][0] + bsum[nt][0];
            float v1 = acc[mt][nt][1] + bsum[nt][1];
            float v2 = acc[mt][nt][2] + bsum[nt][0];
            float v3 = acc[mt][nt][3] + bsum[nt][1];
            const float o0 = __shfl_xor_sync(0xffffffffu, v0, 1);
            const float o1 = __shfl_xor_sync(0xffffffffu, v1, 1);
            const float o2 = __shfl_xor_sync(0xffffffffu, v2, 1);
            const float o3 = __shfl_xor_sync(0xffffffffu, v3, 1);

            const float gi0 = is_if ? v0 : o0;
            const float gf0 = is_if ? v1 : o1;
            const float gg0 = is_if ? o0 : v0;
            const float go0 = is_if ? o1 : v1;
            const float gi1 = is_if ? v2 : o2;
            const float gf1 = is_if ? v3 : o3;
            const float gg1 = is_if ? o2 : v2;
            const float go1 = is_if ? o3 : v3;

            const int j = (bn >> 2) + warp_n * 8 + nt * 2 + (q >> 1);
            const float c0v0 = c0[(size_t)r * H_DIM + j];
            const float c0v1 = c0[(size_t)(r + 8) * H_DIM + j];

            const float cn0 = sigmoidf_(gf0) * c0v0 + sigmoidf_(gi0) * tanhf(gg0);
            const float cn1 = sigmoidf_(gf1) * c0v1 + sigmoidf_(gi1) * tanhf(gg1);
            const float hn0 = sigmoidf_(go0) * tanhf(cn0);
            const float hn1 = sigmoidf_(go1) * tanhf(cn1);

            if (is_if) {
                out[(size_t)r * H_DIM + j]       = hn0;
                out[(size_t)(r + 8) * H_DIM + j] = hn1;
            } else {
                out[(size_t)B_DIM * H_DIM + (size_t)r * H_DIM + j]       = cn0;
                out[(size_t)B_DIM * H_DIM + (size_t)(r + 8) * H_DIM + j] = cn1;
            }
        }
    }
    #undef LOAD_STAGE
}

// ---------------------------------------------------------------------------
// Launch
// ---------------------------------------------------------------------------
extern "C" void kernel_launch(void* const* d_in, const int* in_sizes, int n_in,
                              void* d_out, int out_size)
{
    const float* x    = (const float*)d_in[0];
    const float* h0   = (const float*)d_in[1];
    const float* c0   = (const float*)d_in[2];
    const float* wih  = (const float*)d_in[3];
    const float* whh  = (const float*)d_in[4];
    const float* b_ih = (const float*)d_in[5];
    const float* b_hh = (const float*)d_in[6];
    float* out = (float*)d_out;

    cudaFuncSetAttribute(lstm_gemm_fused,
                         cudaFuncAttributeMaxDynamicSharedMemorySize, SMEM_TOTAL);

    convert_all<<<16400, 256>>>(x, h0, wih, whh, b_ih, b_hh);

    dim3 grid(N_GATES / BN, B_DIM / BM);                 // (32, 32) = 1024 CTAs
    lstm_gemm_fused<<<grid, NTHREADS, SMEM_TOTAL>>>(c0, out);
}

// round 16
// speedup vs baseline: 1.5808x; 1.0005x over previous
#include <cuda_runtime.h>
#include <cuda_fp16.h>
#include <cstdint>

// ---------------------------------------------------------------------------
// Problem constants
// ---------------------------------------------------------------------------
#define B_DIM 4096
#define H_DIM 1024
#define N_GATES 4096       // 4*H
#define K_DIM  2048        // D + H

// GEMM tiling (single-pass fp16 HMMA, 64x32 warp tiles, BK=64, 2 CTAs/SM)
#define BM 128
#define BN 128
#define BK 64              // 64 fp16 = 128 B rows
#define STAGES 3
#define NT (K_DIM / BK)    // 32 k-tiles
#define NTHREADS 256

// smem per stage: A 128x128B + B 128x128B = 32768 B
#define A_TILE_BYTES 16384
#define B_TILE_BYTES 16384
#define STAGE_BYTES (A_TILE_BYTES + B_TILE_BYTES)           // 32768
#define OFF_B A_TILE_BYTES
#define SMEM_TOTAL (STAGES * STAGE_BYTES)                   // 98304 -> 2 CTAs/SM

// ---------------------------------------------------------------------------
// Scratch (device globals). gB/gBias GATE-INTERLEAVED: n' = j*4+g.
// ---------------------------------------------------------------------------
__device__ __half gA[(size_t)B_DIM * K_DIM];
__device__ __half gB[(size_t)N_GATES * K_DIM];
__device__ float gBias[N_GATES];

// ---------------------------------------------------------------------------
// PTX helpers (sm_80+ portable)
// ---------------------------------------------------------------------------
__device__ __forceinline__ uint32_t smem_u32(const void* p) {
    uint32_t a;
    asm("{ .reg .u64 t; cvta.to.shared.u64 t, %1; cvt.u32.u64 %0, t; }" : "=r"(a) : "l"(p));
    return a;
}

#define CP_ASYNC16(dst, src) \
    asm volatile("cp.async.cg.shared.global [%0], [%1], 16;" \
                 :: "r"(dst), "l"(src) : "memory")
#define CP_COMMIT() asm volatile("cp.async.commit_group;" ::: "memory")
#define CP_WAIT(n)  asm volatile("cp.async.wait_group %0;" :: "n"(n) : "memory")

#define LDSM_X4(r, addr) \
    asm volatile("ldmatrix.sync.aligned.m8n8.x4.shared.b16 {%0,%1,%2,%3}, [%4];" \
                 : "=r"((r)[0]), "=r"((r)[1]), "=r"((r)[2]), "=r"((r)[3]) : "r"(addr))

__device__ __forceinline__ void mma_f16(float* d, const uint32_t* a, const uint32_t* b) {
    asm volatile(
        "mma.sync.aligned.m16n8k16.row.col.f32.f16.f16.f32 "
        "{%0,%1,%2,%3}, {%4,%5,%6,%7}, {%8,%9}, {%0,%1,%2,%3};"
        : "+f"(d[0]), "+f"(d[1]), "+f"(d[2]), "+f"(d[3])
        : "r"(a[0]), "r"(a[1]), "r"(a[2]), "r"(a[3]), "r"(b[0]), "r"(b[1]));
}

__device__ __forceinline__ float sigmoidf_(float v) {
    return 1.0f / (1.0f + __expf(-v));
}

// ---------------------------------------------------------------------------
// Conversion kernel:
//   blocks [0, 8192):      A = [x | h0]  -> gA   (row-identity)
//   blocks [8192, 16384):  B = [wih|whh] -> gB   (rows permuted j*4+g)
//   blocks [16384, 16400): permuted bias sum
// ---------------------------------------------------------------------------
__global__ __launch_bounds__(256)
void convert_all(const float* __restrict__ x,   const float* __restrict__ h0,
                 const float* __restrict__ wih, const float* __restrict__ whh,
                 const float* __restrict__ b_ih, const float* __restrict__ b_hh)
{
    const int bid = blockIdx.x;
    const int tid = threadIdx.x;

    if (bid >= 16384) {                       // bias
        const int np = (bid - 16384) * 256 + tid;        // 0..4095
        const int r = ((np & 3) << 10) | (np >> 2);      // orig row g*1024+j
        gBias[np] = b_ih[r] + b_hh[r];
        return;
    }

    const bool isA = (bid < 8192);
    const int idx = (isA ? bid : bid - 8192) * 256 + tid;  // 4-elem group id
    const int row = idx >> 9;                              // output row
    const int col = (idx & 511) << 2;                      // K column

    int srow = row;
    const float *s0, *s1;
    if (isA) { s0 = x; s1 = h0; }
    else     { s0 = wih; s1 = whh; srow = ((row & 3) << 10) | (row >> 2); }

    const float* src = (col < 1024) ? (s0 + (size_t)srow * 1024 + col)
                                    : (s1 + (size_t)srow * 1024 + (col - 1024));
    float4 v = *reinterpret_cast<const float4*>(src);
    __half2 h01 = __floats2half2_rn(v.x, v.y);
    __half2 h23 = __floats2half2_rn(v.z, v.w);
    __half* dst = isA ? gA : gB;
    const size_t o = (size_t)row * K_DIM + col;
    *reinterpret_cast<__half2*>(dst + o)     = h01;
    *reinterpret_cast<__half2*>(dst + o + 2) = h23;
}

// ---------------------------------------------------------------------------
// Fused single-pass fp16 GEMM + LSTM epilogue.
//   gates = A @ B^T (gate-interleaved cols), fp32 accumulate. BK=64, 32 iters.
//   Register double-buffered mainloop: fragments for ks+1 are loaded BEFORE
//   the MMAs of ks, so LDSM latency hides under the tensor burst (the head
//   is exposed only at ks=0 after each barrier).
// SMEM: 128B rows, chunk' = chunk ^ (row&7) (conflict-free both directions).
// ---------------------------------------------------------------------------
__global__ __launch_bounds__(NTHREADS, 2)
void lstm_gemm_fused(const float* __restrict__ c0, float* __restrict__ out)
{
    extern __shared__ char smem[];
    const uint32_t sb = smem_u32(smem);
    const int tid  = threadIdx.x;
    const int wid  = tid >> 5;
    const int lane = tid & 31;
    const int warp_m = wid >> 2;    // 0..1, 64 rows each
    const int warp_n = wid & 3;     // 0..3, 32 cols each

    const int bm = blockIdx.y * BM;
    const int bn = blockIdx.x * BN;

    float acc[4][4][4];             // [mt][nt][frag]
    #pragma unroll
    for (int mt = 0; mt < 4; mt++)
        #pragma unroll
        for (int nt = 0; nt < 4; nt++)
            #pragma unroll
            for (int j = 0; j < 4; j++)
                acc[mt][nt][j] = 0.0f;

    // ---- ldmatrix addressing (128B rows, swizzle chunk ^ (row&7)) ----
    const int a_row = warp_m * 64 + (lane & 15);              // + mt*16
    const int s_a   = a_row & 7;
    const int a_c0  = lane >> 4;                              // 0/1
    const int b_row = warp_n * 32 + ((lane >> 4) << 3) + (lane & 7);  // + g*16
    const int s_b   = b_row & 7;
    const int b_c0  = (lane >> 3) & 1;

    // ---- cp.async: A 1024 chunks + B 1024 chunks, 8 per thread ----
    const int r0 = tid >> 3;                 // 0..31
    const int cc = tid & 7;                  // 16B chunk in 128B row
    const uint32_t dstoff = (uint32_t)(r0 * 128 + ((cc ^ (r0 & 7)) << 4));
    const __half* pA = gA + (size_t)(bm + r0) * K_DIM + cc * 8;
    const __half* pB = gB + (size_t)(bn + r0) * K_DIM + cc * 8;
    const size_t RSTEP = (size_t)32 * K_DIM;   // +32 rows ((r0+32j)&7 == r0&7)

    #define LOAD_STAGE(bufidx, k0) do {                                         \
        const uint32_t s_ = sb + (bufidx) * STAGE_BYTES + dstoff;               \
        CP_ASYNC16(s_,                  pA + (k0));                             \
        CP_ASYNC16(s_ + 4096,           pA + (k0) + RSTEP);                     \
        CP_ASYNC16(s_ + 8192,           pA + (k0) + 2 * RSTEP);                 \
        CP_ASYNC16(s_ + 12288,          pA + (k0) + 3 * RSTEP);                 \
        CP_ASYNC16(s_ + OFF_B,          pB + (k0));                             \
        CP_ASYNC16(s_ + OFF_B + 4096,   pB + (k0) + RSTEP);                     \
        CP_ASYNC16(s_ + OFF_B + 8192,   pB + (k0) + 2 * RSTEP);                 \
        CP_ASYNC16(s_ + OFF_B + 12288,  pB + (k0) + 3 * RSTEP);                 \
    } while (0)

    // Load fragments for k16-step `ks` from `stage` into buffer slot `slot`.
    #define LOAD_FRAGS(slot, stage, ks) do {                                    \
        const int ca_ = (((ks) * 2 + a_c0) ^ s_a) << 4;                         \
        _Pragma("unroll")                                                       \
        for (int mt_ = 0; mt_ < 4; mt_++) {                                     \
            const uint32_t aa_ = (stage) + (a_row + mt_ * 16) * 128 + ca_;      \
            LDSM_X4(a_fr[slot][mt_], aa_);                                      \
        }                                                                       \
        const int cb_ = (((ks) * 2 + b_c0) ^ s_b) << 4;                         \
        _Pragma("unroll")                                                       \
        for (int g_ = 0; g_ < 2; g_++) {                                        \
            const uint32_t ba_ = (stage) + OFF_B + (b_row + g_ * 16) * 128 + cb_;\
            LDSM_X4(b_fr[slot][g_], ba_);                                       \
        }                                                                       \
    } while (0)

    #define DO_MMAS(slot) do {                                                  \
        _Pragma("unroll")                                                       \
        for (int g_ = 0; g_ < 2; g_++)                                          \
            _Pragma("unroll")                                                   \
            for (int h_ = 0; h_ < 2; h_++)                                      \
                _Pragma("unroll")                                               \
                for (int mt_ = 0; mt_ < 4; mt_++)                               \
                    mma_f16(acc[mt_][g_ * 2 + h_], a_fr[slot][mt_],             \
                            &b_fr[slot][g_][h_ * 2]);                           \
    } while (0)

    // prologue: stages 0,1
    LOAD_STAGE(0, 0);
    CP_COMMIT();
    LOAD_STAGE(1, BK);
    CP_COMMIT();

    uint32_t a_fr[2][4][4], b_fr[2][2][4];   // double-buffered fragments

    int cbuf = 0, lbuf = 2;
    for (int t = 0; t < NT; t++) {
        CP_WAIT(1);
        __syncthreads();
        if (t + 2 < NT)
            LOAD_STAGE(lbuf, (t + 2) * BK);
        CP_COMMIT();

        const uint32_t stage = sb + cbuf * STAGE_BYTES;

        // preload ks=0 fragments, then per-ks: load ks+1 frags BEFORE MMAs(ks)
        LOAD_FRAGS(0, stage, 0);
        LOAD_FRAGS(1, stage, 1);
        DO_MMAS(0);
        LOAD_FRAGS(0, stage, 2);
        DO_MMAS(1);
        LOAD_FRAGS(1, stage, 3);
        DO_MMAS(0);
        DO_MMAS(1);

        if (++cbuf == STAGES) cbuf = 0;
        if (++lbuf == STAGES) lbuf = 0;
    }

    // ---- fused LSTM epilogue ----
    const int q = lane & 3;
    const bool is_if = ((q & 1) == 0);

    float bsum[4][2];
    #pragma unroll
    for (int nt = 0; nt < 4; nt++) {
        const int c = bn + warp_n * 32 + nt * 8 + q * 2;
        bsum[nt][0] = gBias[c];
        bsum[nt][1] = gBias[c + 1];
    }

    #pragma unroll
    for (int mt = 0; mt < 4; mt++) {
        const int r = bm + warp_m * 64 + mt * 16 + (lane >> 2);
        #pragma unroll
        for (int nt = 0; nt < 4; nt++) {
            float v0 = acc[mt][nt][0] + bsum[nt][0];
            float v1 = acc[mt][nt][1] + bsum[nt][1];
            float v2 = acc[mt][nt][2] + bsum[nt][0];
            float v3 = acc[mt][nt][3] + bsum[nt][1];
            const float o0 = __shfl_xor_sync(0xffffffffu, v0, 1);
            const float o1 = __shfl_xor_sync(0xffffffffu, v1, 1);
            const float o2 = __shfl_xor_sync(0xffffffffu, v2, 1);
            const float o3 = __shfl_xor_sync(0xffffffffu, v3, 1);

            const float gi0 = is_if ? v0 : o0;
            const float gf0 = is_if ? v1 : o1;
            const float gg0 = is_if ? o0 : v0;
            const float go0 = is_if ? o1 : v1;
            const float gi1 = is_if ? v2 : o2;
            const float gf1 = is_if ? v3 : o3;
            const float gg1 = is_if ? o2 : v2;
            const float go1 = is_if ? o3 : v3;

            const int j = (bn >> 2) + warp_n * 8 + nt * 2 + (q >> 1);
            const float c0v0 = c0[(size_t)r * H_DIM + j];
            const float c0v1 = c0[(size_t)(r + 8) * H_DIM + j];

            const float cn0 = sigmoidf_(gf0) * c0v0 + sigmoidf_(gi0) * tanhf(gg0);
            const float cn1 = sigmoidf_(gf1) * c0v1 + sigmoidf_(gi1) * tanhf(gg1);
            const float hn0 = sigmoidf_(go0) * tanhf(cn0);
            const float hn1 = sigmoidf_(go1) * tanhf(cn1);

            if (is_if) {
                out[(size_t)r * H_DIM + j]       = hn0;
                out[(size_t)(r + 8) * H_DIM + j] = hn1;
            } else {
                out[(size_t)B_DIM * H_DIM + (size_t)r * H_DIM + j]       = cn0;
                out[(size_t)B_DIM * H_DIM + (size_t)(r + 8) * H_DIM + j] = cn1;
            }
        }
    }
    #undef LOAD_STAGE
    #undef LOAD_FRAGS
    #undef DO_MMAS
}

// ---------------------------------------------------------------------------
// Launch
// ---------------------------------------------------------------------------
extern "C" void kernel_launch(void* const* d_in, const int* in_sizes, int n_in,
                              void* d_out, int out_size)
{
    const float* x    = (const float*)d_in[0];
    const float* h0   = (const float*)d_in[1];
    const float* c0   = (const float*)d_in[2];
    const float* wih  = (const float*)d_in[3];
    const float* whh  = (const float*)d_in[4];
    const float* b_ih = (const float*)d_in[5];
    const float* b_hh = (const float*)d_in[6];
    float* out = (float*)d_out;

    cudaFuncSetAttribute(lstm_gemm_fused,
                         cudaFuncAttributeMaxDynamicSharedMemorySize, SMEM_TOTAL);

    convert_all<<<16400, 256>>>(x, h0, wih, whh, b_ih, b_hh);

    dim3 grid(N_GATES / BN, B_DIM / BM);                 // (32, 32) = 1024 CTAs
    lstm_gemm_fused<<<grid, NTHREADS, SMEM_TOTAL>>>(c0, out);
}